// round 10
// baseline (speedup 1.0000x reference)
#include <cuda_runtime.h>
#include <cuda_bf16.h>
#include <math.h>
#include <float.h>

// Problem constants
#define BB 4
#define SS 2048
#define DD 1024
#define HH 16
#define DK 64
#define ALPHA 0.7f
#define OMALPHA 0.3f

// GEMM tile
#define BM 128
#define BN 128
#define BKK 32
#define SROW 40                       // padded smem row in bf16 (80B)
#define GEMM_BUF (BM * SROW)
#define GEMM_BUFB (GEMM_BUF * 2)      // 10240 bytes
#define GEMM_SMEM (3 * 2 * GEMM_BUFB) // 61440 bytes

// Attention
#define VROW 72
#define ATT_BUF (64 * VROW)
#define ATT_BUFB (ATT_BUF * 2)        // 9216 bytes
#define ATT_SMEM (3 * 2 * ATT_BUFB)   // 55296 bytes
#define NTILES (SS / 64)              // 32

// Scratch (device globals; allocation-free per harness rules)
__device__ float g_stats[BB * DD * 5];
__device__ int   g_anymaskzero;

__device__ __nv_bfloat16 g_Xh[BB * SS * DD];
__device__ __nv_bfloat16 g_Wh[3 * DD * DD];
__device__ __nv_bfloat16 g_Qh[BB * SS * DD];
__device__ __nv_bfloat16 g_Kh[BB * SS * DD];
__device__ __nv_bfloat16 g_Vh[BB * SS * DD];

// ---- mma / async helpers ----
__device__ __forceinline__ unsigned sptr(const void* p) {
    return (unsigned)__cvta_generic_to_shared(p);
}
__device__ __forceinline__ void ldsm4(unsigned* r, unsigned addr) {
    asm volatile("ldmatrix.sync.aligned.m8n8.x4.shared.b16 {%0,%1,%2,%3}, [%4];\n"
                 : "=r"(r[0]), "=r"(r[1]), "=r"(r[2]), "=r"(r[3]) : "r"(addr));
}
__device__ __forceinline__ void ldsm4t(unsigned* r, unsigned addr) {
    asm volatile("ldmatrix.sync.aligned.m8n8.x4.trans.shared.b16 {%0,%1,%2,%3}, [%4];\n"
                 : "=r"(r[0]), "=r"(r[1]), "=r"(r[2]), "=r"(r[3]) : "r"(addr));
}
__device__ __forceinline__ void mma_bf16(float* c, const unsigned* a, const unsigned* b) {
    asm volatile("mma.sync.aligned.m16n8k16.row.col.f32.bf16.bf16.f32 "
                 "{%0,%1,%2,%3}, {%4,%5,%6,%7}, {%8,%9}, {%0,%1,%2,%3};\n"
                 : "+f"(c[0]), "+f"(c[1]), "+f"(c[2]), "+f"(c[3])
                 : "r"(a[0]), "r"(a[1]), "r"(a[2]), "r"(a[3]), "r"(b[0]), "r"(b[1]));
}
__device__ __forceinline__ void mma_bf16s(float* c, const unsigned* a, unsigned b0, unsigned b1) {
    asm volatile("mma.sync.aligned.m16n8k16.row.col.f32.bf16.bf16.f32 "
                 "{%0,%1,%2,%3}, {%4,%5,%6,%7}, {%8,%9}, {%0,%1,%2,%3};\n"
                 : "+f"(c[0]), "+f"(c[1]), "+f"(c[2]), "+f"(c[3])
                 : "r"(a[0]), "r"(a[1]), "r"(a[2]), "r"(a[3]), "r"(b0), "r"(b1));
}
__device__ __forceinline__ unsigned packbf2(float lo, float hi) {
    __nv_bfloat162 v = __floats2bfloat162_rn(lo, hi);
    return *(unsigned*)&v;
}
__device__ __forceinline__ void cpasync16(unsigned dst, const void* src) {
    asm volatile("cp.async.cg.shared.global [%0], [%1], 16;\n" :: "r"(dst), "l"(src));
}
__device__ __forceinline__ void cpcommit() {
    asm volatile("cp.async.commit_group;\n");
}
template<int N> __device__ __forceinline__ void cpwait() {
    asm volatile("cp.async.wait_group %0;\n" :: "n"(N));
}

// ---------------------------------------------------------------------------
// Kernel 0: zero scratch stats + mask flag (must precede prep_kernel)
// ---------------------------------------------------------------------------
__global__ void zero_scratch_kernel() {
    int i = blockIdx.x * blockDim.x + threadIdx.x;
    if (i < BB * DD * 5) g_stats[i] = 0.0f;
    if (i == 0) g_anymaskzero = 0;
}

// ---------------------------------------------------------------------------
// Fused prep: X->bf16 (blocks 0..8191), W->bf16 x3 (blocks 8192..11263),
// mask scan (blocks 11264..11775).
// ---------------------------------------------------------------------------
__global__ void prep_kernel(const float* __restrict__ x,
                            const float* __restrict__ qw,
                            const float* __restrict__ kw,
                            const float* __restrict__ vw,
                            const int* __restrict__ mask, int maskN) {
    const int bid = blockIdx.x;
    const int tid = threadIdx.x;
    if (bid < 8192) {
        const int i = bid * 256 + tid;              // n4 = 2097152
        const float4 v = ((const float4*)x)[i];
        __nv_bfloat162* dp = (__nv_bfloat162*)g_Xh;
        dp[2 * i]     = __floats2bfloat162_rn(v.x, v.y);
        dp[2 * i + 1] = __floats2bfloat162_rn(v.z, v.w);
    } else if (bid < 8192 + 3072) {
        const int seg = (bid - 8192) >> 10;         // 0..2
        const int i = ((bid - 8192) & 1023) * 256 + tid;   // n4 = 262144
        const float* src = (seg == 0) ? qw : (seg == 1) ? kw : vw;
        const float4 v = ((const float4*)src)[i];
        __nv_bfloat162* dp = (__nv_bfloat162*)(g_Wh + (size_t)seg * DD * DD);
        dp[2 * i]     = __floats2bfloat162_rn(v.x, v.y);
        dp[2 * i + 1] = __floats2bfloat162_rn(v.z, v.w);
    } else {
        int i = (bid - 8192 - 3072) * 256 + tid;
        const int stride = 512 * 256;
        bool z = false;
        for (; i < maskN; i += stride)
            if (mask[i] == 0) z = true;
        if (z) atomicExch(&g_anymaskzero, 1);
    }
}

// ---------------------------------------------------------------------------
// Kernel 1: Fourier stats
// ---------------------------------------------------------------------------
__global__ void fourier_stats_kernel(const float* __restrict__ x) {
    const int b = blockIdx.y;
    const int sc = blockIdx.x;
    const int tid = threadIdx.x;
    const float w0 = 6.283185307179586476925286766559f / (float)SS;

    float acc[4][5];
#pragma unroll
    for (int i = 0; i < 4; i++)
#pragma unroll
        for (int k = 0; k < 5; k++) acc[i][k] = 0.0f;

    for (int si = 0; si < SS / 16; si++) {
        const int s = sc * (SS / 16) + si;
        float s1, c1;
        sincosf(w0 * (float)s, &s1, &c1);
        const float c2 = c1 * c1 - s1 * s1;
        const float s2 = 2.0f * s1 * c1;
        const float* xp = x + ((size_t)(b * SS + s)) * DD + tid;
#pragma unroll
        for (int i = 0; i < 4; i++) {
            const float v = xp[i * 256];
            acc[i][0] += v;
            acc[i][1] += v * c1;
            acc[i][2] += v * s1;
            acc[i][3] += v * c2;
            acc[i][4] += v * s2;
        }
    }
#pragma unroll
    for (int i = 0; i < 4; i++) {
        const int d = i * 256 + tid;
        float* st = &g_stats[(b * DD + d) * 5];
        atomicAdd(&st[0], acc[i][0]);
        atomicAdd(&st[1], acc[i][1]);
        atomicAdd(&st[2], acc[i][2]);
        atomicAdd(&st[3], acc[i][3]);
        atomicAdd(&st[4], acc[i][4]);
    }
}

// ---------------------------------------------------------------------------
// Kernel 3: DSP branch + LayerNorm -> ALPHA*dsp into out
// ---------------------------------------------------------------------------
__global__ void dsp_ln_kernel(const float* __restrict__ x,
                              const float* __restrict__ sqrt_beta,
                              const float* __restrict__ gamma,
                              const float* __restrict__ lnb,
                              float* __restrict__ out) {
    const int bt = blockIdx.x;
    const int b = bt >> 11;
    const int t = bt & (SS - 1);
    const int tid = threadIdx.x;
    const float w0 = 6.283185307179586476925286766559f / (float)SS;

    float s1, c1;
    sincosf(w0 * (float)t, &s1, &c1);
    const float c2 = c1 * c1 - s1 * s1;
    const float s2 = 2.0f * s1 * c1;

    float y[4];
    float sum = 0.0f, sq = 0.0f;
#pragma unroll
    for (int i = 0; i < 4; i++) {
        const int d = i * 256 + tid;
        const float* st = &g_stats[(b * DD + d) * 5];
        const float lp = (st[0] + 2.0f * (st[1] * c1 + st[2] * s1)
                                + 2.0f * (st[3] * c2 + st[4] * s2)) * (1.0f / (float)SS);
        const float v = x[((size_t)(b * SS + t)) * DD + d];
        const float be = sqrt_beta[d];
        const float b2 = be * be;
        const float yy = (1.0f + b2) * v + (1.0f - b2) * lp;
        y[i] = yy;
        sum += yy;
        sq += yy * yy;
    }

    __shared__ float red[18];
#pragma unroll
    for (int o = 16; o; o >>= 1) {
        sum += __shfl_down_sync(0xffffffffu, sum, o);
        sq  += __shfl_down_sync(0xffffffffu, sq, o);
    }
    const int w = tid >> 5, ln = tid & 31;
    if (ln == 0) { red[w] = sum; red[w + 8] = sq; }
    __syncthreads();
    if (tid == 0) {
        float s = 0.0f, ssq = 0.0f;
        for (int i = 0; i < 8; i++) { s += red[i]; ssq += red[i + 8]; }
        red[16] = s; red[17] = ssq;
    }
    __syncthreads();
    sum = red[16]; sq = red[17];

    const float mu = sum * (1.0f / (float)DD);
    const float var = sq * (1.0f / (float)DD) - mu * mu;
    const float rs = rsqrtf(var + 1e-12f);
#pragma unroll
    for (int i = 0; i < 4; i++) {
        const int d = i * 256 + tid;
        out[((size_t)(b * SS + t)) * DD + d] =
            ALPHA * ((y[i] - mu) * rs * gamma[d] + lnb[d]);
    }
}

// ---------------------------------------------------------------------------
// Kernel 4: QKV GEMM, bf16 mma, 3-stage cp.async pipeline, 1 sync/tile.
// Q output pre-scaled by 1/8 (folded attention score scale).
// ---------------------------------------------------------------------------
__global__ __launch_bounds__(256) void gemm_qkv_mma(
    const float* __restrict__ qb, const float* __restrict__ kb,
    const float* __restrict__ vb) {
    const int z = blockIdx.z;
    const __nv_bfloat16* W = g_Wh + (size_t)z * DD * DD;
    const float* bias;
    __nv_bfloat16* ohi;
    if (z == 0)      { bias = qb; ohi = g_Qh; }
    else if (z == 1) { bias = kb; ohi = g_Kh; }
    else             { bias = vb; ohi = g_Vh; }
    const float oscale = (z == 0) ? 0.125f : 1.0f;

    extern __shared__ char smem_dyn[];
    __nv_bfloat16* sA = (__nv_bfloat16*)smem_dyn;
    __nv_bfloat16* sB = sA + 3 * GEMM_BUF;

    const int tid = threadIdx.x;
    const int lane = tid & 31, warp = tid >> 5;
    const int wm = warp & 1, wn = warp >> 1;
    const int m0 = blockIdx.y * BM, n0 = blockIdx.x * BN;

    float acc[4][4][4];
#pragma unroll
    for (int a = 0; a < 4; a++)
#pragma unroll
        for (int b = 0; b < 4; b++)
#pragma unroll
            for (int c = 0; c < 4; c++) acc[a][b][c] = 0.0f;

    const int grow = tid >> 1;
    const int gcol = (tid & 1) * 16;
    const __nv_bfloat16* pA = g_Xh + (size_t)(m0 + grow) * DD + gcol;
    const __nv_bfloat16* pB = W + (size_t)(n0 + grow) * DD + gcol;

    const unsigned dA0 = sptr(sA + grow * SROW + gcol);
    const unsigned dB0 = sptr(sB + grow * SROW + gcol);

    const unsigned aBase0 = sptr(sA) + ((unsigned)(wm * 64 + (lane & 15))) * (SROW * 2) + (lane >> 4) * 16;
    const int j = lane >> 3;
    const unsigned bBase0 = sptr(sB) + ((unsigned)(wn * 32 + (j >> 1) * 8 + (lane & 7))) * (SROW * 2) + (j & 1) * 16;
    const unsigned ROWB = SROW * 2;

    const int NT = DD / BKK;
#pragma unroll
    for (int p = 0; p < 2; p++) {
        const unsigned off = p * GEMM_BUFB;
        const int kk = p * BKK;
        cpasync16(dA0 + off, pA + kk);  cpasync16(dA0 + off + 16, pA + kk + 8);
        cpasync16(dB0 + off, pB + kk);  cpasync16(dB0 + off + 16, pB + kk + 8);
        cpcommit();
    }

    for (int it = 0; it < NT; it++) {
        if (it < NT - 1) cpwait<1>(); else cpwait<0>();
        __syncthreads();
        if (it + 2 < NT) {
            const unsigned off = ((it + 2) % 3) * GEMM_BUFB;
            const int kk = (it + 2) * BKK;
            cpasync16(dA0 + off, pA + kk);  cpasync16(dA0 + off + 16, pA + kk + 8);
            cpasync16(dB0 + off, pB + kk);  cpasync16(dB0 + off + 16, pB + kk + 8);
            cpcommit();
        }

        const unsigned coff = (it % 3) * GEMM_BUFB;
#pragma unroll
        for (int ks = 0; ks < 2; ks++) {
            unsigned a[4][4], b[2][4];
#pragma unroll
            for (int mt = 0; mt < 4; mt++)
                ldsm4(a[mt], aBase0 + coff + mt * 16 * ROWB + ks * 32);
#pragma unroll
            for (int np = 0; np < 2; np++)
                ldsm4(b[np], bBase0 + coff + np * 16 * ROWB + ks * 32);
#pragma unroll
            for (int mt = 0; mt < 4; mt++)
#pragma unroll
                for (int nt = 0; nt < 4; nt++)
                    mma_bf16(acc[mt][nt], a[mt], &b[nt >> 1][(nt & 1) * 2]);
        }
    }

#pragma unroll
    for (int nt = 0; nt < 4; nt++) {
        const int col = n0 + wn * 32 + nt * 8 + (lane & 3) * 2;
        const float bx = bias[col], by = bias[col + 1];
#pragma unroll
        for (int mt = 0; mt < 4; mt++) {
            const int r = m0 + wm * 64 + mt * 16 + (lane >> 2);
            *(__nv_bfloat162*)&ohi[(size_t)r * DD + col] =
                __floats2bfloat162_rn((acc[mt][nt][0] + bx) * oscale,
                                      (acc[mt][nt][1] + by) * oscale);
            *(__nv_bfloat162*)&ohi[(size_t)(r + 8) * DD + col] =
                __floats2bfloat162_rn((acc[mt][nt][2] + bx) * oscale,
                                      (acc[mt][nt][3] + by) * oscale);
        }
    }
}

// ---------------------------------------------------------------------------
// Kernel 5: HMMA flash attention, 32 q-rows per warp (2 strips), no-max
// softmax, 3-stage cp.async pipeline. grid (SS/256, B*H), 256 threads.
// ---------------------------------------------------------------------------
__global__ __launch_bounds__(256) void attn_mma_kernel(
    const int* __restrict__ mask, float* __restrict__ out) {
    const int qt = blockIdx.x;
    const int bh = blockIdx.y;
    const int b = bh >> 4, h = bh & 15;
    const int tid = threadIdx.x;
    const int lane = tid & 31, warp = tid >> 5;

    extern __shared__ char smem_dyn[];
    __nv_bfloat16* sK = (__nv_bfloat16*)smem_dyn;
    __nv_bfloat16* sV = sK + 3 * ATT_BUF;

    const int m0 = qt * 256 + warp * 32;
    const int rA = m0 + (lane >> 2);          // strip A rows rA, rA+8
    const int rB = rA + 16;                   // strip B rows rB, rB+8
    const int lc = (lane & 3) * 2;

    // Q fragments for both strips (pre-scaled by 1/8 in GEMM epilogue)
    unsigned qA[4][4], qB[4][4];
#pragma unroll
    for (int kk = 0; kk < 4; kk++) {
        const int dbase = h * 64 + kk * 16 + lc;
        qA[kk][0] = *(const unsigned*)&g_Qh[(size_t)(b * SS + rA) * DD + dbase];
        qA[kk][1] = *(const unsigned*)&g_Qh[(size_t)(b * SS + rA + 8) * DD + dbase];
        qA[kk][2] = *(const unsigned*)&g_Qh[(size_t)(b * SS + rA) * DD + dbase + 8];
        qA[kk][3] = *(const unsigned*)&g_Qh[(size_t)(b * SS + rA + 8) * DD + dbase + 8];
        qB[kk][0] = *(const unsigned*)&g_Qh[(size_t)(b * SS + rB) * DD + dbase];
        qB[kk][1] = *(const unsigned*)&g_Qh[(size_t)(b * SS + rB + 8) * DD + dbase];
        qB[kk][2] = *(const unsigned*)&g_Qh[(size_t)(b * SS + rB) * DD + dbase + 8];
        qB[kk][3] = *(const unsigned*)&g_Qh[(size_t)(b * SS + rB + 8) * DD + dbase + 8];
    }

    float oA[8][4], oB[8][4];
#pragma unroll
    for (int nt = 0; nt < 8; nt++)
#pragma unroll
        for (int c = 0; c < 4; c++) { oA[nt][c] = 0.0f; oB[nt][c] = 0.0f; }
    float lA0 = 0.0f, lA1 = 0.0f, lB0 = 0.0f, lB1 = 0.0f;

    const int anyzero = g_anymaskzero;

    const int row0 = tid >> 3;
    const int c8   = (tid & 7) * 8;
    const unsigned sKd = sptr(sK + row0 * VROW + c8);
    const unsigned sVd = sptr(sV + row0 * VROW + c8);
    const unsigned rowStrideB = 32 * VROW * 2;

    const int j = lane >> 3;
    const unsigned bRowCol = ((unsigned)((j >> 1) * 8 + (lane & 7))) * (VROW * 2) + (j & 1) * 16;
    const unsigned kBase = sptr(sK) + bRowCol;
    const unsigned vBase = sptr(sV) + bRowCol;
    const unsigned ROWB = VROW * 2;

#pragma unroll
    for (int p = 0; p < 2; p++) {
        const unsigned off = p * ATT_BUFB;
        const size_t g0 = (size_t)(b * SS + p * 64 + row0) * DD + h * 64 + c8;
        cpasync16(sKd + off, &g_Kh[g0]);
        cpasync16(sKd + off + rowStrideB, &g_Kh[g0 + (size_t)32 * DD]);
        cpasync16(sVd + off, &g_Vh[g0]);
        cpasync16(sVd + off + rowStrideB, &g_Vh[g0 + (size_t)32 * DD]);
        cpcommit();
    }

    for (int kt = 0; kt < NTILES; kt++) {
        if (kt < NTILES - 1) cpwait<1>(); else cpwait<0>();
        __syncthreads();
        if (kt + 2 < NTILES) {
            const unsigned off = ((kt + 2) % 3) * ATT_BUFB;
            const size_t gn = (size_t)(b * SS + (kt + 2) * 64 + row0) * DD + h * 64 + c8;
            cpasync16(sKd + off, &g_Kh[gn]);
            cpasync16(sKd + off + rowStrideB, &g_Kh[gn + (size_t)32 * DD]);
            cpasync16(sVd + off, &g_Vh[gn]);
            cpasync16(sVd + off + rowStrideB, &g_Vh[gn + (size_t)32 * DD]);
            cpcommit();
        }

        const unsigned coff = (kt % 3) * ATT_BUFB;
        const int j0 = kt * 64;

        // ---- S = Q K^T for both strips ----
        float sA[8][4], sB[8][4];
#pragma unroll
        for (int nt = 0; nt < 8; nt++)
#pragma unroll
            for (int c = 0; c < 4; c++) { sA[nt][c] = 0.0f; sB[nt][c] = 0.0f; }

#pragma unroll
        for (int kk = 0; kk < 4; kk++) {
            unsigned kh[4][4];
#pragma unroll
            for (int ng = 0; ng < 4; ng++)
                ldsm4(kh[ng], kBase + coff + ng * 16 * ROWB + kk * 32);
#pragma unroll
            for (int ng = 0; ng < 4; ng++) {
                mma_bf16(sA[ng * 2],     qA[kk], &kh[ng][0]);
                mma_bf16(sA[ng * 2 + 1], qA[kk], &kh[ng][2]);
                mma_bf16(sB[ng * 2],     qB[kk], &kh[ng][0]);
                mma_bf16(sB[ng * 2 + 1], qB[kk], &kh[ng][2]);
            }
        }

        if (anyzero) {
#pragma unroll
            for (int nt = 0; nt < 8; nt++) {
                const int col = j0 + nt * 8 + lc;
                if (mask[(size_t)rA * SS + col] == 0)           sA[nt][0] = -1e30f;
                if (mask[(size_t)rA * SS + col + 1] == 0)       sA[nt][1] = -1e30f;
                if (mask[(size_t)(rA + 8) * SS + col] == 0)     sA[nt][2] = -1e30f;
                if (mask[(size_t)(rA + 8) * SS + col + 1] == 0) sA[nt][3] = -1e30f;
                if (mask[(size_t)rB * SS + col] == 0)           sB[nt][0] = -1e30f;
                if (mask[(size_t)rB * SS + col + 1] == 0)       sB[nt][1] = -1e30f;
                if (mask[(size_t)(rB + 8) * SS + col] == 0)     sB[nt][2] = -1e30f;
                if (mask[(size_t)(rB + 8) * SS + col + 1] == 0) sB[nt][3] = -1e30f;
            }
        }

        // ---- p = exp(s) ----
        unsigned paA[4][4], paB[4][4];
#pragma unroll
        for (int kk2 = 0; kk2 < 4; kk2++) {
            const int na = 2 * kk2, nb = 2 * kk2 + 1;
            {
                const float p00 = __expf(sA[na][0]), p01 = __expf(sA[na][1]);
                const float p10 = __expf(sA[na][2]), p11 = __expf(sA[na][3]);
                const float q00 = __expf(sA[nb][0]), q01 = __expf(sA[nb][1]);
                const float q10 = __expf(sA[nb][2]), q11 = __expf(sA[nb][3]);
                lA0 += p00 + p01 + q00 + q01;
                lA1 += p10 + p11 + q10 + q11;
                paA[kk2][0] = packbf2(p00, p01);
                paA[kk2][1] = packbf2(p10, p11);
                paA[kk2][2] = packbf2(q00, q01);
                paA[kk2][3] = packbf2(q10, q11);
            }
            {
                const float p00 = __expf(sB[na][0]), p01 = __expf(sB[na][1]);
                const float p10 = __expf(sB[na][2]), p11 = __expf(sB[na][3]);
                const float q00 = __expf(sB[nb][0]), q01 = __expf(sB[nb][1]);
                const float q10 = __expf(sB[nb][2]), q11 = __expf(sB[nb][3]);
                lB0 += p00 + p01 + q00 + q01;
                lB1 += p10 + p11 + q10 + q11;
                paB[kk2][0] = packbf2(p00, p01);
                paB[kk2][1] = packbf2(p10, p11);
                paB[kk2][2] = packbf2(q00, q01);
                paB[kk2][3] = packbf2(q10, q11);
            }
        }

        // ---- O += P V (V fragments shared across strips) ----
#pragma unroll
        for (int kk2 = 0; kk2 < 4; kk2++) {
#pragma unroll
            for (int dg = 0; dg < 4; dg++) {
                unsigned vt[4];
                ldsm4t(vt, vBase + coff + kk2 * 16 * ROWB + dg * 32);
                mma_bf16s(oA[dg * 2],     paA[kk2], vt[0], vt[2]);
                mma_bf16s(oA[dg * 2 + 1], paA[kk2], vt[1], vt[3]);
                mma_bf16s(oB[dg * 2],     paB[kk2], vt[0], vt[2]);
                mma_bf16s(oB[dg * 2 + 1], paB[kk2], vt[1], vt[3]);
            }
        }
    }

    lA0 += __shfl_xor_sync(0xffffffffu, lA0, 1);
    lA0 += __shfl_xor_sync(0xffffffffu, lA0, 2);
    lA1 += __shfl_xor_sync(0xffffffffu, lA1, 1);
    lA1 += __shfl_xor_sync(0xffffffffu, lA1, 2);
    lB0 += __shfl_xor_sync(0xffffffffu, lB0, 1);
    lB0 += __shfl_xor_sync(0xffffffffu, lB0, 2);
    lB1 += __shfl_xor_sync(0xffffffffu, lB1, 1);
    lB1 += __shfl_xor_sync(0xffffffffu, lB1, 2);

    const float iA0 = (lA0 > 0.0f) ? (OMALPHA / lA0) : 0.0f;
    const float iA1 = (lA1 > 0.0f) ? (OMALPHA / lA1) : 0.0f;
    const float iB0 = (lB0 > 0.0f) ? (OMALPHA / lB0) : 0.0f;
    const float iB1 = (lB1 > 0.0f) ? (OMALPHA / lB1) : 0.0f;

#pragma unroll
    for (int nt = 0; nt < 8; nt++) {
        const int d = h * 64 + nt * 8 + lc;
        float2* pA0 = (float2*)&out[(size_t)(b * SS + rA) * DD + d];
        float2* pA1 = (float2*)&out[(size_t)(b * SS + rA + 8) * DD + d];
        float2* pB0 = (float2*)&out[(size_t)(b * SS + rB) * DD + d];
        float2* pB1 = (float2*)&out[(size_t)(b * SS + rB + 8) * DD + d];
        float2 vA0 = *pA0, vA1 = *pA1, vB0 = *pB0, vB1 = *pB1;
        vA0.x += oA[nt][0] * iA0; vA0.y += oA[nt][1] * iA0;
        vA1.x += oA[nt][2] * iA1; vA1.y += oA[nt][3] * iA1;
        vB0.x += oB[nt][0] * iB0; vB0.y += oB[nt][1] * iB0;
        vB1.x += oB[nt][2] * iB1; vB1.y += oB[nt][3] * iB1;
        *pA0 = vA0; *pA1 = vA1; *pB0 = vB0; *pB1 = vB1;
    }
}

// ---------------------------------------------------------------------------
extern "C" void kernel_launch(void* const* d_in, const int* in_sizes, int n_in,
                              void* d_out, int out_size) {
    const float* x       = (const float*)d_in[0];
    const int*   mask    = (const int*)d_in[1];
    const float* sb      = (const float*)d_in[2];
    const float* gamma   = (const float*)d_in[3];
    const float* lnb     = (const float*)d_in[4];
    const float* qw      = (const float*)d_in[5];
    const float* qb      = (const float*)d_in[6];
    const float* kw      = (const float*)d_in[7];
    const float* kb      = (const float*)d_in[8];
    const float* vw      = (const float*)d_in[9];
    const float* vb      = (const float*)d_in[10];
    float* out = (float*)d_out;
    const int maskN = in_sizes[1];

    static int attr_done = 0;
    if (!attr_done) {
        cudaFuncSetAttribute(gemm_qkv_mma, cudaFuncAttributeMaxDynamicSharedMemorySize, GEMM_SMEM);
        cudaFuncSetAttribute(attn_mma_kernel, cudaFuncAttributeMaxDynamicSharedMemorySize, ATT_SMEM);
        attr_done = 1;
    }

    zero_scratch_kernel<<<(BB * DD * 5 + 255) / 256, 256>>>();
    prep_kernel<<<8192 + 3072 + 512, 256>>>(x, qw, kw, vw, mask, maskN);
    fourier_stats_kernel<<<dim3(16, BB), 256>>>(x);
    dsp_ln_kernel<<<BB * SS, 256>>>(x, sb, gamma, lnb, out);
    gemm_qkv_mma<<<dim3(DD / BN, BB * SS / BM, 3), 256, GEMM_SMEM>>>(qb, kb, vb);
    attn_mma_kernel<<<dim3(SS / 256, BB * HH), 256, ATT_SMEM>>>(mask, out);
}

// round 11
// speedup vs baseline: 1.2464x; 1.2464x over previous
#include <cuda_runtime.h>
#include <cuda_bf16.h>
#include <math.h>
#include <float.h>

// Problem constants
#define BB 4
#define SS 2048
#define DD 1024
#define HH 16
#define DK 64
#define ALPHA 0.7f
#define OMALPHA 0.3f

// GEMM tile
#define BM 128
#define BN 128
#define BKK 32
#define SROW 40                       // padded smem row in bf16 (80B)
#define GEMM_BUF (BM * SROW)
#define GEMM_BUFB (GEMM_BUF * 2)      // 10240 bytes
#define GEMM_SMEM (3 * 2 * GEMM_BUFB) // 61440 bytes

// Attention
#define VROW 72
#define ATT_BUF (64 * VROW)
#define ATT_BUFB (ATT_BUF * 2)        // 9216 bytes
#define ATT_SMEM (3 * 2 * ATT_BUFB)   // 55296 bytes
#define NTILES (SS / 64)              // 32

// Scratch (device globals; allocation-free per harness rules)
__device__ float g_stats[BB * DD * 5];
__device__ int   g_anymaskzero;

__device__ __nv_bfloat16 g_Xh[BB * SS * DD];
__device__ __nv_bfloat16 g_Wh[3 * DD * DD];
__device__ __nv_bfloat16 g_Qh[BB * SS * DD];
__device__ __nv_bfloat16 g_Kh[BB * SS * DD];
__device__ __nv_bfloat16 g_Vh[BB * SS * DD];

// ---- mma / async helpers ----
__device__ __forceinline__ unsigned sptr(const void* p) {
    return (unsigned)__cvta_generic_to_shared(p);
}
__device__ __forceinline__ void ldsm4(unsigned* r, unsigned addr) {
    asm volatile("ldmatrix.sync.aligned.m8n8.x4.shared.b16 {%0,%1,%2,%3}, [%4];\n"
                 : "=r"(r[0]), "=r"(r[1]), "=r"(r[2]), "=r"(r[3]) : "r"(addr));
}
__device__ __forceinline__ void ldsm4t(unsigned* r, unsigned addr) {
    asm volatile("ldmatrix.sync.aligned.m8n8.x4.trans.shared.b16 {%0,%1,%2,%3}, [%4];\n"
                 : "=r"(r[0]), "=r"(r[1]), "=r"(r[2]), "=r"(r[3]) : "r"(addr));
}
__device__ __forceinline__ void mma_bf16(float* c, const unsigned* a, const unsigned* b) {
    asm volatile("mma.sync.aligned.m16n8k16.row.col.f32.bf16.bf16.f32 "
                 "{%0,%1,%2,%3}, {%4,%5,%6,%7}, {%8,%9}, {%0,%1,%2,%3};\n"
                 : "+f"(c[0]), "+f"(c[1]), "+f"(c[2]), "+f"(c[3])
                 : "r"(a[0]), "r"(a[1]), "r"(a[2]), "r"(a[3]), "r"(b[0]), "r"(b[1]));
}
__device__ __forceinline__ void mma_bf16s(float* c, const unsigned* a, unsigned b0, unsigned b1) {
    asm volatile("mma.sync.aligned.m16n8k16.row.col.f32.bf16.bf16.f32 "
                 "{%0,%1,%2,%3}, {%4,%5,%6,%7}, {%8,%9}, {%0,%1,%2,%3};\n"
                 : "+f"(c[0]), "+f"(c[1]), "+f"(c[2]), "+f"(c[3])
                 : "r"(a[0]), "r"(a[1]), "r"(a[2]), "r"(a[3]), "r"(b0), "r"(b1));
}
__device__ __forceinline__ unsigned packbf2(float lo, float hi) {
    __nv_bfloat162 v = __floats2bfloat162_rn(lo, hi);
    return *(unsigned*)&v;
}
__device__ __forceinline__ void cpasync16(unsigned dst, const void* src) {
    asm volatile("cp.async.cg.shared.global [%0], [%1], 16;\n" :: "r"(dst), "l"(src));
}
__device__ __forceinline__ void cpcommit() {
    asm volatile("cp.async.commit_group;\n");
}
template<int N> __device__ __forceinline__ void cpwait() {
    asm volatile("cp.async.wait_group %0;\n" :: "n"(N));
}

// ---------------------------------------------------------------------------
// Kernel 0: zero scratch stats + mask flag (must precede prep_kernel)
// ---------------------------------------------------------------------------
__global__ void zero_scratch_kernel() {
    int i = blockIdx.x * blockDim.x + threadIdx.x;
    if (i < BB * DD * 5) g_stats[i] = 0.0f;
    if (i == 0) g_anymaskzero = 0;
}

// ---------------------------------------------------------------------------
// Fused prep: X->bf16 (blocks 0..8191), W->bf16 x3 (blocks 8192..11263),
// mask scan (blocks 11264..11775).
// ---------------------------------------------------------------------------
__global__ void prep_kernel(const float* __restrict__ x,
                            const float* __restrict__ qw,
                            const float* __restrict__ kw,
                            const float* __restrict__ vw,
                            const int* __restrict__ mask, int maskN) {
    const int bid = blockIdx.x;
    const int tid = threadIdx.x;
    if (bid < 8192) {
        const int i = bid * 256 + tid;
        const float4 v = ((const float4*)x)[i];
        __nv_bfloat162* dp = (__nv_bfloat162*)g_Xh;
        dp[2 * i]     = __floats2bfloat162_rn(v.x, v.y);
        dp[2 * i + 1] = __floats2bfloat162_rn(v.z, v.w);
    } else if (bid < 8192 + 3072) {
        const int seg = (bid - 8192) >> 10;
        const int i = ((bid - 8192) & 1023) * 256 + tid;
        const float* src = (seg == 0) ? qw : (seg == 1) ? kw : vw;
        const float4 v = ((const float4*)src)[i];
        __nv_bfloat162* dp = (__nv_bfloat162*)(g_Wh + (size_t)seg * DD * DD);
        dp[2 * i]     = __floats2bfloat162_rn(v.x, v.y);
        dp[2 * i + 1] = __floats2bfloat162_rn(v.z, v.w);
    } else {
        int i = (bid - 8192 - 3072) * 256 + tid;
        const int stride = 512 * 256;
        bool z = false;
        for (; i < maskN; i += stride)
            if (mask[i] == 0) z = true;
        if (z) atomicExch(&g_anymaskzero, 1);
    }
}

// ---------------------------------------------------------------------------
// Kernel 1: Fourier stats
// ---------------------------------------------------------------------------
__global__ void fourier_stats_kernel(const float* __restrict__ x) {
    const int b = blockIdx.y;
    const int sc = blockIdx.x;
    const int tid = threadIdx.x;
    const float w0 = 6.283185307179586476925286766559f / (float)SS;

    float acc[4][5];
#pragma unroll
    for (int i = 0; i < 4; i++)
#pragma unroll
        for (int k = 0; k < 5; k++) acc[i][k] = 0.0f;

    for (int si = 0; si < SS / 16; si++) {
        const int s = sc * (SS / 16) + si;
        float s1, c1;
        sincosf(w0 * (float)s, &s1, &c1);
        const float c2 = c1 * c1 - s1 * s1;
        const float s2 = 2.0f * s1 * c1;
        const float* xp = x + ((size_t)(b * SS + s)) * DD + tid;
#pragma unroll
        for (int i = 0; i < 4; i++) {
            const float v = xp[i * 256];
            acc[i][0] += v;
            acc[i][1] += v * c1;
            acc[i][2] += v * s1;
            acc[i][3] += v * c2;
            acc[i][4] += v * s2;
        }
    }
#pragma unroll
    for (int i = 0; i < 4; i++) {
        const int d = i * 256 + tid;
        float* st = &g_stats[(b * DD + d) * 5];
        atomicAdd(&st[0], acc[i][0]);
        atomicAdd(&st[1], acc[i][1]);
        atomicAdd(&st[2], acc[i][2]);
        atomicAdd(&st[3], acc[i][3]);
        atomicAdd(&st[4], acc[i][4]);
    }
}

// ---------------------------------------------------------------------------
// Kernel 3: DSP branch + LayerNorm -> ALPHA*dsp into out
// ---------------------------------------------------------------------------
__global__ void dsp_ln_kernel(const float* __restrict__ x,
                              const float* __restrict__ sqrt_beta,
                              const float* __restrict__ gamma,
                              const float* __restrict__ lnb,
                              float* __restrict__ out) {
    const int bt = blockIdx.x;
    const int b = bt >> 11;
    const int t = bt & (SS - 1);
    const int tid = threadIdx.x;
    const float w0 = 6.283185307179586476925286766559f / (float)SS;

    float s1, c1;
    sincosf(w0 * (float)t, &s1, &c1);
    const float c2 = c1 * c1 - s1 * s1;
    const float s2 = 2.0f * s1 * c1;

    float y[4];
    float sum = 0.0f, sq = 0.0f;
#pragma unroll
    for (int i = 0; i < 4; i++) {
        const int d = i * 256 + tid;
        const float* st = &g_stats[(b * DD + d) * 5];
        const float lp = (st[0] + 2.0f * (st[1] * c1 + st[2] * s1)
                                + 2.0f * (st[3] * c2 + st[4] * s2)) * (1.0f / (float)SS);
        const float v = x[((size_t)(b * SS + t)) * DD + d];
        const float be = sqrt_beta[d];
        const float b2 = be * be;
        const float yy = (1.0f + b2) * v + (1.0f - b2) * lp;
        y[i] = yy;
        sum += yy;
        sq += yy * yy;
    }

    __shared__ float red[18];
#pragma unroll
    for (int o = 16; o; o >>= 1) {
        sum += __shfl_down_sync(0xffffffffu, sum, o);
        sq  += __shfl_down_sync(0xffffffffu, sq, o);
    }
    const int w = tid >> 5, ln = tid & 31;
    if (ln == 0) { red[w] = sum; red[w + 8] = sq; }
    __syncthreads();
    if (tid == 0) {
        float s = 0.0f, ssq = 0.0f;
        for (int i = 0; i < 8; i++) { s += red[i]; ssq += red[i + 8]; }
        red[16] = s; red[17] = ssq;
    }
    __syncthreads();
    sum = red[16]; sq = red[17];

    const float mu = sum * (1.0f / (float)DD);
    const float var = sq * (1.0f / (float)DD) - mu * mu;
    const float rs = rsqrtf(var + 1e-12f);
#pragma unroll
    for (int i = 0; i < 4; i++) {
        const int d = i * 256 + tid;
        out[((size_t)(b * SS + t)) * DD + d] =
            ALPHA * ((y[i] - mu) * rs * gamma[d] + lnb[d]);
    }
}

// ---------------------------------------------------------------------------
// Kernel 4: QKV GEMM, bf16 mma, 3-stage cp.async pipeline, 1 sync/tile.
// Q output pre-scaled by 1/8 (folded attention score scale).
// ---------------------------------------------------------------------------
__global__ __launch_bounds__(256) void gemm_qkv_mma(
    const float* __restrict__ qb, const float* __restrict__ kb,
    const float* __restrict__ vb) {
    const int z = blockIdx.z;
    const __nv_bfloat16* W = g_Wh + (size_t)z * DD * DD;
    const float* bias;
    __nv_bfloat16* ohi;
    if (z == 0)      { bias = qb; ohi = g_Qh; }
    else if (z == 1) { bias = kb; ohi = g_Kh; }
    else             { bias = vb; ohi = g_Vh; }
    const float oscale = (z == 0) ? 0.125f : 1.0f;

    extern __shared__ char smem_dyn[];
    __nv_bfloat16* sA = (__nv_bfloat16*)smem_dyn;
    __nv_bfloat16* sB = sA + 3 * GEMM_BUF;

    const int tid = threadIdx.x;
    const int lane = tid & 31, warp = tid >> 5;
    const int wm = warp & 1, wn = warp >> 1;
    const int m0 = blockIdx.y * BM, n0 = blockIdx.x * BN;

    float acc[4][4][4];
#pragma unroll
    for (int a = 0; a < 4; a++)
#pragma unroll
        for (int b = 0; b < 4; b++)
#pragma unroll
            for (int c = 0; c < 4; c++) acc[a][b][c] = 0.0f;

    const int grow = tid >> 1;
    const int gcol = (tid & 1) * 16;
    const __nv_bfloat16* pA = g_Xh + (size_t)(m0 + grow) * DD + gcol;
    const __nv_bfloat16* pB = W + (size_t)(n0 + grow) * DD + gcol;

    const unsigned dA0 = sptr(sA + grow * SROW + gcol);
    const unsigned dB0 = sptr(sB + grow * SROW + gcol);

    const unsigned aBase0 = sptr(sA) + ((unsigned)(wm * 64 + (lane & 15))) * (SROW * 2) + (lane >> 4) * 16;
    const int j = lane >> 3;
    const unsigned bBase0 = sptr(sB) + ((unsigned)(wn * 32 + (j >> 1) * 8 + (lane & 7))) * (SROW * 2) + (j & 1) * 16;
    const unsigned ROWB = SROW * 2;

    const int NT = DD / BKK;
#pragma unroll
    for (int p = 0; p < 2; p++) {
        const unsigned off = p * GEMM_BUFB;
        const int kk = p * BKK;
        cpasync16(dA0 + off, pA + kk);  cpasync16(dA0 + off + 16, pA + kk + 8);
        cpasync16(dB0 + off, pB + kk);  cpasync16(dB0 + off + 16, pB + kk + 8);
        cpcommit();
    }

    for (int it = 0; it < NT; it++) {
        if (it < NT - 1) cpwait<1>(); else cpwait<0>();
        __syncthreads();
        if (it + 2 < NT) {
            const unsigned off = ((it + 2) % 3) * GEMM_BUFB;
            const int kk = (it + 2) * BKK;
            cpasync16(dA0 + off, pA + kk);  cpasync16(dA0 + off + 16, pA + kk + 8);
            cpasync16(dB0 + off, pB + kk);  cpasync16(dB0 + off + 16, pB + kk + 8);
            cpcommit();
        }

        const unsigned coff = (it % 3) * GEMM_BUFB;
#pragma unroll
        for (int ks = 0; ks < 2; ks++) {
            unsigned a[4][4], b[2][4];
#pragma unroll
            for (int mt = 0; mt < 4; mt++)
                ldsm4(a[mt], aBase0 + coff + mt * 16 * ROWB + ks * 32);
#pragma unroll
            for (int np = 0; np < 2; np++)
                ldsm4(b[np], bBase0 + coff + np * 16 * ROWB + ks * 32);
#pragma unroll
            for (int mt = 0; mt < 4; mt++)
#pragma unroll
                for (int nt = 0; nt < 4; nt++)
                    mma_bf16(acc[mt][nt], a[mt], &b[nt >> 1][(nt & 1) * 2]);
        }
    }

#pragma unroll
    for (int nt = 0; nt < 4; nt++) {
        const int col = n0 + wn * 32 + nt * 8 + (lane & 3) * 2;
        const float bx = bias[col], by = bias[col + 1];
#pragma unroll
        for (int mt = 0; mt < 4; mt++) {
            const int r = m0 + wm * 64 + mt * 16 + (lane >> 2);
            *(__nv_bfloat162*)&ohi[(size_t)r * DD + col] =
                __floats2bfloat162_rn((acc[mt][nt][0] + bx) * oscale,
                                      (acc[mt][nt][1] + by) * oscale);
            *(__nv_bfloat162*)&ohi[(size_t)(r + 8) * DD + col] =
                __floats2bfloat162_rn((acc[mt][nt][2] + bx) * oscale,
                                      (acc[mt][nt][3] + by) * oscale);
        }
    }
}

// ---------------------------------------------------------------------------
// Kernel 5: HMMA flash attention (exact R7 version): 16 q-rows/warp, no-max
// softmax, 3-stage cp.async pipeline, 1 sync/tile. grid (SS/128, B*H), 256 thr.
// ---------------------------------------------------------------------------
__global__ __launch_bounds__(256) void attn_mma_kernel(
    const int* __restrict__ mask, float* __restrict__ out) {
    const int qt = blockIdx.x;
    const int bh = blockIdx.y;
    const int b = bh >> 4, h = bh & 15;
    const int tid = threadIdx.x;
    const int lane = tid & 31, warp = tid >> 5;

    extern __shared__ char smem_dyn[];
    __nv_bfloat16* sK = (__nv_bfloat16*)smem_dyn;
    __nv_bfloat16* sV = sK + 3 * ATT_BUF;

    const int m0 = qt * 128 + warp * 16;
    const int r0 = m0 + (lane >> 2);
    const int r1 = r0 + 8;
    const int lc = (lane & 3) * 2;

    unsigned qh[4][4];
#pragma unroll
    for (int kk = 0; kk < 4; kk++) {
        const int dbase = h * 64 + kk * 16 + lc;
        qh[kk][0] = *(const unsigned*)&g_Qh[(size_t)(b * SS + r0) * DD + dbase];
        qh[kk][1] = *(const unsigned*)&g_Qh[(size_t)(b * SS + r1) * DD + dbase];
        qh[kk][2] = *(const unsigned*)&g_Qh[(size_t)(b * SS + r0) * DD + dbase + 8];
        qh[kk][3] = *(const unsigned*)&g_Qh[(size_t)(b * SS + r1) * DD + dbase + 8];
    }

    float o[8][4];
#pragma unroll
    for (int nt = 0; nt < 8; nt++)
#pragma unroll
        for (int c = 0; c < 4; c++) o[nt][c] = 0.0f;
    float lrow0 = 0.0f, lrow1 = 0.0f;

    const int anyzero = g_anymaskzero;

    const int row0 = tid >> 3;
    const int c8   = (tid & 7) * 8;
    const unsigned sKd = sptr(sK + row0 * VROW + c8);
    const unsigned sVd = sptr(sV + row0 * VROW + c8);
    const unsigned rowStrideB = 32 * VROW * 2;

    const int j = lane >> 3;
    const unsigned bRowCol = ((unsigned)((j >> 1) * 8 + (lane & 7))) * (VROW * 2) + (j & 1) * 16;
    const unsigned kBase = sptr(sK) + bRowCol;
    const unsigned vBase = sptr(sV) + bRowCol;
    const unsigned ROWB = VROW * 2;

#pragma unroll
    for (int p = 0; p < 2; p++) {
        const unsigned off = p * ATT_BUFB;
        const size_t g0 = (size_t)(b * SS + p * 64 + row0) * DD + h * 64 + c8;
        cpasync16(sKd + off, &g_Kh[g0]);
        cpasync16(sKd + off + rowStrideB, &g_Kh[g0 + (size_t)32 * DD]);
        cpasync16(sVd + off, &g_Vh[g0]);
        cpasync16(sVd + off + rowStrideB, &g_Vh[g0 + (size_t)32 * DD]);
        cpcommit();
    }

    for (int kt = 0; kt < NTILES; kt++) {
        if (kt < NTILES - 1) cpwait<1>(); else cpwait<0>();
        __syncthreads();
        if (kt + 2 < NTILES) {
            const unsigned off = ((kt + 2) % 3) * ATT_BUFB;
            const size_t gn = (size_t)(b * SS + (kt + 2) * 64 + row0) * DD + h * 64 + c8;
            cpasync16(sKd + off, &g_Kh[gn]);
            cpasync16(sKd + off + rowStrideB, &g_Kh[gn + (size_t)32 * DD]);
            cpasync16(sVd + off, &g_Vh[gn]);
            cpasync16(sVd + off + rowStrideB, &g_Vh[gn + (size_t)32 * DD]);
            cpcommit();
        }

        const unsigned coff = (kt % 3) * ATT_BUFB;
        const int j0 = kt * 64;

        float s[8][4];
#pragma unroll
        for (int nt = 0; nt < 8; nt++)
#pragma unroll
            for (int c = 0; c < 4; c++) s[nt][c] = 0.0f;

#pragma unroll
        for (int kk = 0; kk < 4; kk++) {
            unsigned kh[4][4];
#pragma unroll
            for (int ng = 0; ng < 4; ng++)
                ldsm4(kh[ng], kBase + coff + ng * 16 * ROWB + kk * 32);
#pragma unroll
            for (int ng = 0; ng < 4; ng++) {
                mma_bf16(s[ng * 2],     qh[kk], &kh[ng][0]);
                mma_bf16(s[ng * 2 + 1], qh[kk], &kh[ng][2]);
            }
        }

        if (anyzero) {
#pragma unroll
            for (int nt = 0; nt < 8; nt++) {
                const int col = j0 + nt * 8 + lc;
                if (mask[(size_t)r0 * SS + col] == 0)     s[nt][0] = -1e30f;
                if (mask[(size_t)r0 * SS + col + 1] == 0) s[nt][1] = -1e30f;
                if (mask[(size_t)r1 * SS + col] == 0)     s[nt][2] = -1e30f;
                if (mask[(size_t)r1 * SS + col + 1] == 0) s[nt][3] = -1e30f;
            }
        }

        unsigned pa[4][4];
#pragma unroll
        for (int kk2 = 0; kk2 < 4; kk2++) {
            const int na = 2 * kk2, nb = 2 * kk2 + 1;
            const float pa00 = __expf(s[na][0]), pa01 = __expf(s[na][1]);
            const float pa10 = __expf(s[na][2]), pa11 = __expf(s[na][3]);
            const float pb00 = __expf(s[nb][0]), pb01 = __expf(s[nb][1]);
            const float pb10 = __expf(s[nb][2]), pb11 = __expf(s[nb][3]);
            lrow0 += pa00 + pa01 + pb00 + pb01;
            lrow1 += pa10 + pa11 + pb10 + pb11;
            pa[kk2][0] = packbf2(pa00, pa01);
            pa[kk2][1] = packbf2(pa10, pa11);
            pa[kk2][2] = packbf2(pb00, pb01);
            pa[kk2][3] = packbf2(pb10, pb11);
        }

#pragma unroll
        for (int kk2 = 0; kk2 < 4; kk2++) {
#pragma unroll
            for (int dg = 0; dg < 4; dg++) {
                unsigned vt[4];
                ldsm4t(vt, vBase + coff + kk2 * 16 * ROWB + dg * 32);
                mma_bf16s(o[dg * 2],     pa[kk2], vt[0], vt[2]);
                mma_bf16s(o[dg * 2 + 1], pa[kk2], vt[1], vt[3]);
            }
        }
    }

    lrow0 += __shfl_xor_sync(0xffffffffu, lrow0, 1);
    lrow0 += __shfl_xor_sync(0xffffffffu, lrow0, 2);
    lrow1 += __shfl_xor_sync(0xffffffffu, lrow1, 1);
    lrow1 += __shfl_xor_sync(0xffffffffu, lrow1, 2);

    const float invl0 = (lrow0 > 0.0f) ? (OMALPHA / lrow0) : 0.0f;
    const float invl1 = (lrow1 > 0.0f) ? (OMALPHA / lrow1) : 0.0f;

#pragma unroll
    for (int nt = 0; nt < 8; nt++) {
        const int d = h * 64 + nt * 8 + lc;
        float2* p0 = (float2*)&out[(size_t)(b * SS + r0) * DD + d];
        float2* p1 = (float2*)&out[(size_t)(b * SS + r1) * DD + d];
        float2 v0 = *p0, v1 = *p1;
        v0.x += o[nt][0] * invl0; v0.y += o[nt][1] * invl0;
        v1.x += o[nt][2] * invl1; v1.y += o[nt][3] * invl1;
        *p0 = v0; *p1 = v1;
    }
}

// ---------------------------------------------------------------------------
extern "C" void kernel_launch(void* const* d_in, const int* in_sizes, int n_in,
                              void* d_out, int out_size) {
    const float* x       = (const float*)d_in[0];
    const int*   mask    = (const int*)d_in[1];
    const float* sb      = (const float*)d_in[2];
    const float* gamma   = (const float*)d_in[3];
    const float* lnb     = (const float*)d_in[4];
    const float* qw      = (const float*)d_in[5];
    const float* qb      = (const float*)d_in[6];
    const float* kw      = (const float*)d_in[7];
    const float* kb      = (const float*)d_in[8];
    const float* vw      = (const float*)d_in[9];
    const float* vb      = (const float*)d_in[10];
    float* out = (float*)d_out;
    const int maskN = in_sizes[1];

    static cudaStream_t s2 = nullptr;
    static cudaEvent_t evFork = nullptr, evJoin = nullptr;
    static int attr_done = 0;
    if (!attr_done) {
        cudaFuncSetAttribute(gemm_qkv_mma, cudaFuncAttributeMaxDynamicSharedMemorySize, GEMM_SMEM);
        cudaFuncSetAttribute(attn_mma_kernel, cudaFuncAttributeMaxDynamicSharedMemorySize, ATT_SMEM);
        cudaStreamCreateWithFlags(&s2, cudaStreamNonBlocking);
        cudaEventCreateWithFlags(&evFork, cudaEventDisableTiming);
        cudaEventCreateWithFlags(&evJoin, cudaEventDisableTiming);
        attr_done = 1;
    }

    // main stream (legacy default, captured by harness)
    zero_scratch_kernel<<<(BB * DD * 5 + 255) / 256, 256>>>();
    cudaEventRecord(evFork, 0);

    // side stream: DSP branch (x-only inputs; needs zeroed g_stats)
    cudaStreamWaitEvent(s2, evFork, 0);
    fourier_stats_kernel<<<dim3(16, BB), 256, 0, s2>>>(x);
    dsp_ln_kernel<<<BB * SS, 256, 0, s2>>>(x, sb, gamma, lnb, out);
    cudaEventRecord(evJoin, s2);

    // main stream: GSP branch prep + GEMM (independent of side stream)
    prep_kernel<<<8192 + 3072 + 512, 256>>>(x, qw, kw, vw, mask, maskN);
    gemm_qkv_mma<<<dim3(DD / BN, BB * SS / BM, 3), 256, GEMM_SMEM>>>(qb, kb, vb);

    // join: attention accumulates into dsp_ln's output
    cudaStreamWaitEvent(0, evJoin, 0);
    attn_mma_kernel<<<dim3(SS / 128, BB * HH), 256, ATT_SMEM>>>(mask, out);
}